// round 6
// baseline (speedup 1.0000x reference)
#include <cuda_runtime.h>
#include <math_constants.h>

// pred_hm [256, 68, 64, 64] f32, center [256,2] f32, scale [256] f32
// -> out [256, 68, 2] f32.
#define NB    256
#define NC    68
#define HH    64
#define WW    64
#define HW    4096           // 64*64
#define NTHR  128            // threads per CTA
#define F4S   8              // float4 chunks per thread: 4096/4/128
#define NWRP  (NTHR / 32)
#define NTILE (NB * NC)      // 17408
#define GRID  888            // 6 CTAs/SM * 148 SMs -> single wave
#define BASEC (NTILE / GRID) // 19 tiles per CTA
#define REMC  (NTILE - GRID * BASEC) // 536 CTAs get one extra tile

__device__ __forceinline__ void issue_tile_copies(const float* __restrict__ hm,
                                                  int bc, unsigned smem_dst, int t)
{
    const float4* __restrict__ src4 =
        reinterpret_cast<const float4*>(hm + (size_t)bc * HW);
    #pragma unroll
    for (int j = 0; j < F4S; ++j) {
        const int f = j * NTHR + t;
        asm volatile("cp.async.cg.shared.global [%0], [%1], 16;\n"
                     :: "r"(smem_dst + f * 16), "l"(src4 + f));
    }
    asm volatile("cp.async.commit_group;\n");
}

__global__ __launch_bounds__(NTHR)
void face_landmark_kernel(const float* __restrict__ hm,
                          const float* __restrict__ center,
                          const float* __restrict__ scale,
                          float* __restrict__ out)
{
    __shared__ float buf[2][HW];               // 2 x 16 KB double buffer
    __shared__ float sv[NWRP];
    __shared__ int   si[NWRP];

    const int cta  = blockIdx.x;
    const int t    = threadIdx.x;
    const int warp = t >> 5;
    const int cnt   = BASEC + (cta < REMC ? 1 : 0);
    const int start = cta * BASEC + min(cta, REMC);

    const unsigned sb[2] = {
        (unsigned)__cvta_generic_to_shared(buf[0]),
        (unsigned)__cvta_generic_to_shared(buf[1])
    };

    // prologue: tile 'start' into buffer 0
    issue_tile_copies(hm, start, sb[0], t);

    for (int i = 0; i < cnt; ++i) {
        const int bc = start + i;

        // keep the pipe fed: next tile's copies in flight during this compute
        if (i + 1 < cnt) {
            issue_tile_copies(hm, bc + 1, sb[(i + 1) & 1], t);
            asm volatile("cp.async.wait_group 1;\n");   // tile i's group done
        } else {
            asm volatile("cp.async.wait_group 0;\n");
        }

        const float* __restrict__ tile = buf[i & 1];

        // ---- thread-local argmax over this thread's own copied elements ----
        float best = -CUDART_INF_F;
        int   bidx = 0;
        #pragma unroll
        for (int j = 0; j < F4S; ++j) {
            const int f    = j * NTHR + t;
            const float4 v = reinterpret_cast<const float4*>(tile)[f];
            const int base = f << 2;
            if (v.x > best) { best = v.x; bidx = base;     }
            if (v.y > best) { best = v.y; bidx = base + 1; }
            if (v.z > best) { best = v.z; bidx = base + 2; }
            if (v.w > best) { best = v.w; bidx = base + 3; }
        }

        // ---- warp reduction: max value, tie-break to min flat index ----
        #pragma unroll
        for (int off = 16; off > 0; off >>= 1) {
            float ov = __shfl_down_sync(0xffffffffu, best, off);
            int   oi = __shfl_down_sync(0xffffffffu, bidx, off);
            if (ov > best || (ov == best && oi < bidx)) { best = ov; bidx = oi; }
        }
        if ((t & 31) == 0) { sv[warp] = best; si[warp] = bidx; }
        __syncthreads();   // tile fully visible + sv/si ready

        if (t == 0) {
            #pragma unroll
            for (int w = 1; w < NWRP; ++w) {
                if (sv[w] > best || (sv[w] == best && si[w] < bidx)) {
                    best = sv[w]; bidx = si[w];
                }
            }

            // ---- subpixel refine (sign of central differences) ----
            const int iX = bidx & (WW - 1);
            const int iY = bidx >> 6;
            float px = (float)iX + 1.0f;
            float py = (float)iY + 1.0f;

            const int iXc = min(max(iX, 1), WW - 2);
            const int iYc = min(max(iY, 1), HH - 2);
            const float dx = tile[iYc * WW + iXc + 1] - tile[iYc * WW + iXc - 1];
            const float dy = tile[(iYc + 1) * WW + iXc] - tile[(iYc - 1) * WW + iXc];
            const bool interior = (iX > 0) && (iX < WW - 1) &&
                                  (iY > 0) && (iY < HH - 1);

            const float sx = (dx > 0.0f) ? 0.25f : ((dx < 0.0f) ? -0.25f : 0.0f);
            const float sy = (dy > 0.0f) ? 0.25f : ((dy < 0.0f) ? -0.25f : 0.0f);
            px += (interior ? sx : 0.0f) - 0.5f;
            py += (interior ? sy : 0.0f) - 0.5f;

            // ---- inverse affine: x' = px*h/64 + cx - 0.5h ----
            const int   b  = bc / NC;
            const float h  = 200.0f * scale[b];
            const float r  = h * (1.0f / (float)HH);
            out[2 * bc]     = px * r + center[2 * b]     - 0.5f * h;
            out[2 * bc + 1] = py * r + center[2 * b + 1] - 0.5f * h;
        }
        // protect buf[i&1] (reused at i+2) and sv/si (reused at i+1)
        // while thread 0 finishes the epilogue reads above.
        __syncthreads();
    }
}

extern "C" void kernel_launch(void* const* d_in, const int* in_sizes, int n_in,
                              void* d_out, int out_size)
{
    const float* pred_hm = (const float*)d_in[0];   // [256,68,64,64]
    const float* center  = (const float*)d_in[1];   // [256,2]
    const float* scale   = (const float*)d_in[2];   // [256]
    float* out = (float*)d_out;                     // [256,68,2]

    face_landmark_kernel<<<GRID, NTHR>>>(pred_hm, center, scale, out);
}

// round 7
// speedup vs baseline: 1.0908x; 1.0908x over previous
#include <cuda_runtime.h>
#include <math_constants.h>

// pred_hm [256, 68, 64, 64] f32, center [256,2] f32, scale [256] f32
// -> out [256, 68, 2] f32.
#define NB   256
#define NC   68
#define HH   64
#define WW   64
#define HW   4096          // 64*64
#define TILE_BYTES (HW * 4)
#define NTHR 128           // threads per CTA
#define F4S  8             // float4 chunks per thread: 4096/4/128
#define NWRP (NTHR / 32)

__global__ __launch_bounds__(NTHR)
void face_landmark_kernel(const float* __restrict__ hm,
                          const float* __restrict__ center,
                          const float* __restrict__ scale,
                          float* __restrict__ out)
{
    __shared__ __align__(16) float tile[HW];       // 16 KB staged tile
    __shared__ __align__(8)  unsigned long long mbar;
    __shared__ float sv[NWRP];
    __shared__ int   si[NWRP];

    const int bc = blockIdx.x;                 // 0 .. NB*NC-1
    const int t  = threadIdx.x;

    const unsigned smem_tile = (unsigned)__cvta_generic_to_shared(tile);
    const unsigned smem_mbar = (unsigned)__cvta_generic_to_shared(&mbar);

    // ---- init mbarrier, then one 16KB TMA bulk copy for the whole tile ----
    if (t == 0) {
        asm volatile("mbarrier.init.shared.b64 [%0], %1;"
                     :: "r"(smem_mbar), "r"(1) : "memory");
    }
    __syncthreads();
    asm volatile("fence.proxy.async.shared::cta;" ::: "memory");

    if (t == 0) {
        asm volatile("mbarrier.arrive.expect_tx.shared.b64 _, [%0], %1;"
                     :: "r"(smem_mbar), "r"((unsigned)TILE_BYTES) : "memory");
        const void* gsrc = (const void*)(hm + (size_t)bc * HW);
        asm volatile("cp.async.bulk.shared::cta.global.mbarrier::complete_tx::bytes "
                     "[%0], [%1], %2, [%3];"
                     :: "r"(smem_tile), "l"(gsrc), "r"((unsigned)TILE_BYTES),
                        "r"(smem_mbar) : "memory");
    }

    // ---- wait for the bulk copy (HW sleep, acquire) ----
    {
        unsigned done;
        asm volatile(
            "{\n\t.reg .pred p;\n\t"
            "mbarrier.try_wait.parity.acquire.cta.shared::cta.b64 p, [%1], %2;\n\t"
            "selp.b32 %0, 1, 0, p;\n\t}"
            : "=r"(done) : "r"(smem_mbar), "r"(0u) : "memory");
        if (!done) {
            asm volatile(
                "{\n\t.reg .pred P1;\n\t"
                "WAIT_LOOP_%=:\n\t"
                "mbarrier.try_wait.parity.acquire.cta.shared::cta.b64 P1, [%0], %1, 0x989680;\n\t"
                "@P1 bra.uni WAIT_DONE_%=;\n\t"
                "bra.uni WAIT_LOOP_%=;\n\t"
                "WAIT_DONE_%=:\n\t}"
                :: "r"(smem_mbar), "r"(0u) : "memory");
        }
    }

    // ---- thread-local argmax (strict >, ascending index => first occurrence) ----
    float best = -CUDART_INF_F;
    int   bidx = 0;
    #pragma unroll
    for (int j = 0; j < F4S; ++j) {
        const int f    = j * NTHR + t;
        const float4 v = reinterpret_cast<const float4*>(tile)[f];
        const int base = f << 2;
        if (v.x > best) { best = v.x; bidx = base;     }
        if (v.y > best) { best = v.y; bidx = base + 1; }
        if (v.z > best) { best = v.z; bidx = base + 2; }
        if (v.w > best) { best = v.w; bidx = base + 3; }
    }

    // ---- warp reduction: max value, tie-break to min flat index ----
    #pragma unroll
    for (int off = 16; off > 0; off >>= 1) {
        float ov = __shfl_down_sync(0xffffffffu, best, off);
        int   oi = __shfl_down_sync(0xffffffffu, bidx, off);
        if (ov > best || (ov == best && oi < bidx)) { best = ov; bidx = oi; }
    }

    const int warp = t >> 5;
    if ((t & 31) == 0) { sv[warp] = best; si[warp] = bidx; }
    __syncthreads();

    if (t == 0) {
        #pragma unroll
        for (int w = 1; w < NWRP; ++w) {
            if (sv[w] > best || (sv[w] == best && si[w] < bidx)) {
                best = sv[w]; bidx = si[w];
            }
        }

        // ---- subpixel refine (sign of central differences), smem reads ----
        const int iX = bidx & (WW - 1);        // 0-based col
        const int iY = bidx >> 6;              // 0-based row
        float px = (float)iX + 1.0f;
        float py = (float)iY + 1.0f;

        const int iXc = min(max(iX, 1), WW - 2);
        const int iYc = min(max(iY, 1), HH - 2);
        const float dx = tile[iYc * WW + iXc + 1] - tile[iYc * WW + iXc - 1];
        const float dy = tile[(iYc + 1) * WW + iXc] - tile[(iYc - 1) * WW + iXc];
        const bool interior = (iX > 0) && (iX < WW - 1) && (iY > 0) && (iY < HH - 1);

        const float sx = (dx > 0.0f) ? 0.25f : ((dx < 0.0f) ? -0.25f : 0.0f);
        const float sy = (dy > 0.0f) ? 0.25f : ((dy < 0.0f) ? -0.25f : 0.0f);
        px += (interior ? sx : 0.0f) - 0.5f;
        py += (interior ? sy : 0.0f) - 0.5f;

        // ---- inverse affine: x' = px*h/64 + cx - 0.5h ----
        const int   b  = bc / NC;
        const float h  = 200.0f * scale[b];
        const float r  = h * (1.0f / (float)HH);
        out[2 * bc]     = px * r + center[2 * b]     - 0.5f * h;
        out[2 * bc + 1] = py * r + center[2 * b + 1] - 0.5f * h;
    }
}

extern "C" void kernel_launch(void* const* d_in, const int* in_sizes, int n_in,
                              void* d_out, int out_size)
{
    const float* pred_hm = (const float*)d_in[0];   // [256,68,64,64]
    const float* center  = (const float*)d_in[1];   // [256,2]
    const float* scale   = (const float*)d_in[2];   // [256]
    float* out = (float*)d_out;                     // [256,68,2]

    face_landmark_kernel<<<NB * NC, NTHR>>>(pred_hm, center, scale, out);
}

// round 8
// speedup vs baseline: 1.0916x; 1.0007x over previous
#include <cuda_runtime.h>
#include <math_constants.h>

// pred_hm [256, 68, 64, 64] f32, center [256,2] f32, scale [256] f32
// -> out [256, 68, 2] f32.
#define NB   256
#define NC   68
#define HH   64
#define WW   64
#define HW   4096          // 64*64
#define NTHR 128           // threads per CTA
#define NWRP (NTHR / 32)
#define HALF 4             // 4 float4 chunks via cp.async + 4 via LDG

__global__ __launch_bounds__(NTHR, 16)
void face_landmark_kernel(const float* __restrict__ hm,
                          const float* __restrict__ center,
                          const float* __restrict__ scale,
                          float* __restrict__ out)
{
    __shared__ __align__(16) float tile_lo[HW / 2];   // 8 KB: elements 0..2047
    __shared__ float sv[NWRP];
    __shared__ int   si[NWRP];

    const int bc = blockIdx.x;                 // 0 .. NB*NC-1
    const int t  = threadIdx.x;
    const float4* __restrict__ src4 =
        reinterpret_cast<const float4*>(hm + (size_t)bc * HW);

    // ---- stage low half (f = 0..511) via cp.async: in-flight bytes in smem ----
    {
        const unsigned sb = (unsigned)__cvta_generic_to_shared(tile_lo);
        #pragma unroll
        for (int j = 0; j < HALF; ++j) {
            const int f = j * NTHR + t;        // 0..511
            asm volatile("cp.async.cg.shared.global [%0], [%1], 16;\n"
                         :: "r"(sb + f * 16), "l"(src4 + f));
        }
        asm volatile("cp.async.commit_group;\n");
    }

    // ---- load high half (f = 512..1023) via LDG.128: in-flight bytes in RF ----
    float4 r0 = src4[4 * NTHR + t];
    float4 r1 = src4[5 * NTHR + t];
    float4 r2 = src4[6 * NTHR + t];
    float4 r3 = src4[7 * NTHR + t];

    // ---- consume in ascending flat-index order (strict > = first occurrence) ----
    float best = -CUDART_INF_F;
    int   bidx = 0;

    asm volatile("cp.async.wait_group 0;\n");
    #pragma unroll
    for (int j = 0; j < HALF; ++j) {
        const int f    = j * NTHR + t;
        const float4 v = reinterpret_cast<const float4*>(tile_lo)[f];
        const int base = f << 2;
        if (v.x > best) { best = v.x; bidx = base;     }
        if (v.y > best) { best = v.y; bidx = base + 1; }
        if (v.z > best) { best = v.z; bidx = base + 2; }
        if (v.w > best) { best = v.w; bidx = base + 3; }
    }
    {
        const int b0 = (4 * NTHR + t) << 2;
        if (r0.x > best) { best = r0.x; bidx = b0;     }
        if (r0.y > best) { best = r0.y; bidx = b0 + 1; }
        if (r0.z > best) { best = r0.z; bidx = b0 + 2; }
        if (r0.w > best) { best = r0.w; bidx = b0 + 3; }
        const int b1 = (5 * NTHR + t) << 2;
        if (r1.x > best) { best = r1.x; bidx = b1;     }
        if (r1.y > best) { best = r1.y; bidx = b1 + 1; }
        if (r1.z > best) { best = r1.z; bidx = b1 + 2; }
        if (r1.w > best) { best = r1.w; bidx = b1 + 3; }
        const int b2 = (6 * NTHR + t) << 2;
        if (r2.x > best) { best = r2.x; bidx = b2;     }
        if (r2.y > best) { best = r2.y; bidx = b2 + 1; }
        if (r2.z > best) { best = r2.z; bidx = b2 + 2; }
        if (r2.w > best) { best = r2.w; bidx = b2 + 3; }
        const int b3 = (7 * NTHR + t) << 2;
        if (r3.x > best) { best = r3.x; bidx = b3;     }
        if (r3.y > best) { best = r3.y; bidx = b3 + 1; }
        if (r3.z > best) { best = r3.z; bidx = b3 + 2; }
        if (r3.w > best) { best = r3.w; bidx = b3 + 3; }
    }

    // ---- warp reduction: max value, tie-break to min flat index ----
    #pragma unroll
    for (int off = 16; off > 0; off >>= 1) {
        float ov = __shfl_down_sync(0xffffffffu, best, off);
        int   oi = __shfl_down_sync(0xffffffffu, bidx, off);
        if (ov > best || (ov == best && oi < bidx)) { best = ov; bidx = oi; }
    }

    const int warp = t >> 5;
    if ((t & 31) == 0) { sv[warp] = best; si[warp] = bidx; }
    __syncthreads();

    if (t == 0) {
        #pragma unroll
        for (int w = 1; w < NWRP; ++w) {
            if (sv[w] > best || (sv[w] == best && si[w] < bidx)) {
                best = sv[w]; bidx = si[w];
            }
        }

        // ---- subpixel refine: neighbor reads from global (L2-resident) ----
        const int iX = bidx & (WW - 1);        // 0-based col
        const int iY = bidx >> 6;              // 0-based row
        float px = (float)iX + 1.0f;
        float py = (float)iY + 1.0f;

        const int iXc = min(max(iX, 1), WW - 2);
        const int iYc = min(max(iY, 1), HH - 2);
        const float* __restrict__ base = hm + (size_t)bc * HW;
        const float dx = base[iYc * WW + iXc + 1] - base[iYc * WW + iXc - 1];
        const float dy = base[(iYc + 1) * WW + iXc] - base[(iYc - 1) * WW + iXc];
        const bool interior = (iX > 0) && (iX < WW - 1) && (iY > 0) && (iY < HH - 1);

        const float sx = (dx > 0.0f) ? 0.25f : ((dx < 0.0f) ? -0.25f : 0.0f);
        const float sy = (dy > 0.0f) ? 0.25f : ((dy < 0.0f) ? -0.25f : 0.0f);
        px += (interior ? sx : 0.0f) - 0.5f;
        py += (interior ? sy : 0.0f) - 0.5f;

        // ---- inverse affine: x' = px*h/64 + cx - 0.5h ----
        const int   b  = bc / NC;
        const float h  = 200.0f * scale[b];
        const float r  = h * (1.0f / (float)HH);
        out[2 * bc]     = px * r + center[2 * b]     - 0.5f * h;
        out[2 * bc + 1] = py * r + center[2 * b + 1] - 0.5f * h;
    }
}

extern "C" void kernel_launch(void* const* d_in, const int* in_sizes, int n_in,
                              void* d_out, int out_size)
{
    const float* pred_hm = (const float*)d_in[0];   // [256,68,64,64]
    const float* center  = (const float*)d_in[1];   // [256,2]
    const float* scale   = (const float*)d_in[2];   // [256]
    float* out = (float*)d_out;                     // [256,68,2]

    face_landmark_kernel<<<NB * NC, NTHR>>>(pred_hm, center, scale, out);
}